// round 13
// baseline (speedup 1.0000x reference)
#include <cuda_runtime.h>
#include <cuda_bf16.h>
#include <cstdint>
#include <cstddef>

// ---------------- problem constants ----------------
#define BB    64
#define NNODE 1023
#define EE    256
#define HH    512
#define COLS  2048      // 4*H gate columns [i|o|u|f]
#define KTOT  768       // E + H
#define VOCAB 2000
#define MAXMR 16384     // max rows in a recurrent level (level 8: 256*64)

// ---------------- device scratch (allocation-free) ----------------
__device__ __nv_bfloat16 g_WTh[(size_t)COLS * KTOT];   // W^T hi  [n][k]
__device__ __nv_bfloat16 g_WTl[(size_t)COLS * KTOT];   // W^T lo
__device__ float         g_bc[COLS];                   // packed bias
__device__ __nv_bfloat16 g_Eh[2048 * EE];              // emb_table split (padded to 2048 rows)
__device__ __nv_bfloat16 g_El[2048 * EE];
__device__ float         g_ptab[(size_t)VOCAB * COLS]; // emb_table @ Wx + bias
__device__ __nv_bfloat16 g_Ah[2][(size_t)MAXMR * HH];  // hsum split, double-buffered by level parity
__device__ __nv_bfloat16 g_Al[2][(size_t)MAXMR * HH];
__device__ float         g_c[(size_t)BB * NNODE * HH];

// ---------------- helpers ----------------
__device__ __forceinline__ uint32_t smem_u32(const void* p) {
    uint32_t a;
    asm("{ .reg .u64 t; cvta.to.shared.u64 t, %1; cvt.u32.u64 %0, t; }" : "=r"(a) : "l"(p));
    return a;
}
__device__ __forceinline__ void cp_async16(uint32_t saddr, const void* g) {
    asm volatile("cp.async.cg.shared.global [%0], [%1], 16;"
                 :: "r"(saddr), "l"(__cvta_generic_to_global(g)) : "memory");
}
#define CP_COMMIT() asm volatile("cp.async.commit_group;" ::: "memory")
#define CP_WAIT(n)  asm volatile("cp.async.wait_group %0;" :: "n"(n) : "memory")

#define LDSM4(r, addr) \
    asm volatile("ldmatrix.sync.aligned.m8n8.x4.shared.b16 {%0,%1,%2,%3}, [%4];" \
        : "=r"((r)[0]), "=r"((r)[1]), "=r"((r)[2]), "=r"((r)[3]) : "r"(addr))

#define MMA16816(d, a, b) \
    asm volatile("mma.sync.aligned.m16n8k16.row.col.f32.bf16.bf16.f32 " \
        "{%0,%1,%2,%3}, {%4,%5,%6,%7}, {%8,%9}, {%0,%1,%2,%3};" \
        : "+f"((d)[0]), "+f"((d)[1]), "+f"((d)[2]), "+f"((d)[3]) \
        : "r"((a)[0]), "r"((a)[1]), "r"((a)[2]), "r"((a)[3]), "r"((b)[0]), "r"((b)[1]))

__device__ __forceinline__ void split2(float v, __nv_bfloat16& hi, __nv_bfloat16& lo) {
    hi = __float2bfloat16(v);
    lo = __float2bfloat16(v - __bfloat162float(hi));
}
// fast gates (MUFU-based): ~1e-7 rel error
__device__ __forceinline__ float sigf(float x)  { return __fdividef(1.f, 1.f + __expf(-x)); }
__device__ __forceinline__ float tanhff(float x){ return __fdividef(2.f, 1.f + __expf(-2.f * x)) - 1.f; }

// ---------------- coalesced transpose pack of W^T hi/lo ----------------
__global__ void packT_kernel(const float* __restrict__ W_iou, const float* __restrict__ W_f) {
    __shared__ float tile[32][33];
    int n0 = blockIdx.x * 32, k0 = blockIdx.y * 32;
    int tx = threadIdx.x, ty = threadIdx.y;      // (32, 8)
    #pragma unroll
    for (int j = 0; j < 4; j++) {
        int k = k0 + ty + j * 8;
        int n = n0 + tx;
        float w = (n < 3 * HH) ? W_iou[k * (3 * HH) + n] : W_f[k * HH + (n - 3 * HH)];
        tile[ty + j * 8][tx] = w;
    }
    __syncthreads();
    #pragma unroll
    for (int j = 0; j < 4; j++) {
        int n = n0 + ty + j * 8;
        int k = k0 + tx;
        float w = tile[tx][ty + j * 8];
        __nv_bfloat16 hi, lo; split2(w, hi, lo);
        g_WTh[(size_t)n * KTOT + k] = hi;
        g_WTl[(size_t)n * KTOT + k] = lo;
    }
}

// ---------------- split emb table (pad to 2048 rows) + bias pack ----------------
__global__ void esplit_kernel(const float* __restrict__ emb,
                              const float* __restrict__ b_iou, const float* __restrict__ b_f) {
    int idx = blockIdx.x * blockDim.x + threadIdx.x;   // over 2048*256
    if (idx >= 2048 * EE) return;
    int r = idx >> 8, k = idx & 255;
    float v = (r < VOCAB) ? emb[r * EE + k] : 0.f;
    __nv_bfloat16 hi, lo; split2(v, hi, lo);
    g_Eh[idx] = hi; g_El[idx] = lo;
    if (idx < COLS)
        g_bc[idx] = (idx < 3 * HH) ? b_iou[idx] : b_f[idx - 3 * HH];
}

// ---------------- leaf gates over sibling pairs (float4 over k) ----------------
__global__ void leaf_gate(const int* __restrict__ ast) {
    int idx = blockIdx.x * blockDim.x + threadIdx.x;   // over 256*64*128
    if (idx >= 256 * 64 * (HH / 4)) return;
    int k = (idx & 127) * 4;
    int t = idx >> 7;                                  // pair*64 + b
    int b = t & 63, pr = t >> 6;                       // pair 0..255
    int n1 = 511 + 2 * pr;                             // odd leaf of the pair
    int tok1 = ast[b * NNODE + n1];
    int tok2 = ast[b * NNODE + n1 + 1];
    const float* p1 = g_ptab + (size_t)tok1 * COLS + k;
    const float* p2 = g_ptab + (size_t)tok2 * COLS + k;
    float4 i1 = *(const float4*)&p1[0],      i2 = *(const float4*)&p2[0];
    float4 o1 = *(const float4*)&p1[HH],     o2 = *(const float4*)&p2[HH];
    float4 u1 = *(const float4*)&p1[2 * HH], u2 = *(const float4*)&p2[2 * HH];
    float4 c1, c2, hs;
    c1.x = sigf(i1.x) * tanhff(u1.x);  c2.x = sigf(i2.x) * tanhff(u2.x);
    c1.y = sigf(i1.y) * tanhff(u1.y);  c2.y = sigf(i2.y) * tanhff(u2.y);
    c1.z = sigf(i1.z) * tanhff(u1.z);  c2.z = sigf(i2.z) * tanhff(u2.z);
    c1.w = sigf(i1.w) * tanhff(u1.w);  c2.w = sigf(i2.w) * tanhff(u2.w);
    hs.x = sigf(o1.x) * tanhff(c1.x) + sigf(o2.x) * tanhff(c2.x);
    hs.y = sigf(o1.y) * tanhff(c1.y) + sigf(o2.y) * tanhff(c2.y);
    hs.z = sigf(o1.z) * tanhff(c1.z) + sigf(o2.z) * tanhff(c2.z);
    hs.w = sigf(o1.w) * tanhff(c1.w) + sigf(o2.w) * tanhff(c2.w);
    size_t gi1 = ((size_t)n1 * 64 + b) * HH + k;
    *(float4*)&g_c[gi1] = c1;
    *(float4*)&g_c[gi1 + 64 * HH] = c2;
    __nv_bfloat16 h0, l0, h1, l1, h2, l2, h3, l3;
    split2(hs.x, h0, l0); split2(hs.y, h1, l1);
    split2(hs.z, h2, l2); split2(hs.w, h3, l3);
    size_t po = (size_t)(pr * 64 + b) * HH + k;        // parent local row at level 8
    __nv_bfloat162 hh[2] = {__nv_bfloat162(h0, h1), __nv_bfloat162(h2, h3)};
    __nv_bfloat162 ll[2] = {__nv_bfloat162(l0, l1), __nv_bfloat162(l2, l3)};
    *(uint2*)&g_Ah[0][po] = *(uint2*)hh;
    *(uint2*)&g_Al[0][po] = *(uint2*)ll;
}

// ---------------- bf16x3 mma.sync GEMM: 512 thr, 4x4 warps, CTA 128 x NW ----------------
// K consumed in 64-wide chunks (144B-stride smem rows; 4 k16 sub-steps per chunk).
// NW=64/128: 3-stage;  NW=256: 2-stage
// TABLE=true : g_ptab = Eh/El @ W[0:256] + bias                         (K=256)
// TABLE=false: fused: act = ptab[tok] + hsum@W[256:768]; gates -> c, parent hsum-split
//   NT>=4 (NW>=128): gate-interleaved B layout; warp owns all 4 gates for WN/4 k's
//                    -> in-register gate epilogue; only h staged through smem
//   NT==2 (NW=64):   classic layout + smem epilogue (tail + root)
template <int KDIM, bool TABLE, int NW>
__global__ __launch_bounds__(512, 1)
void mma_gemm(const int* __restrict__ ast, int base, int mrows, float* __restrict__ out, int rp) {
    constexpr int WN     = NW / 4;            // warp n-width: 16 / 32 / 64
    constexpr int NT     = WN / 8;            // n-subtiles per warp: 2 / 4 / 8
    constexpr int ASPLIT = 128 * 144;         // 18432 bytes per A split
    constexpr int BOFF   = 2 * ASPLIT;        // 36864
    constexpr int BSPLIT = NW * 144;          // bytes per B split
    constexpr int STAGE  = BOFF + 2 * BSPLIT;
    constexpr int NSTG   = (NW >= 256) ? 2 : 3;
    constexpr int FS     = NW + NW / 32;      // fbuf row stride (classic epilogue)
    constexpr int NC     = KDIM / 64;
    constexpr int KOFF   = TABLE ? 0 : EE;
    constexpr bool FRAG  = (!TABLE) && (NT >= 4);   // fragment gate epilogue
    constexpr int NTG    = (NT >= 4) ? NT / 4 : 1;  // s-subtiles per gate
    constexpr int KW     = WN / 4;            // k's per warp (fragment layout)

    extern __shared__ char smem[];
    const uint32_t sbase = smem_u32(smem);
    const int tid = threadIdx.x;
    const int lane = tid & 31, wid = tid >> 5;
    const int wm = wid >> 2, wn = wid & 3;    // warp grid 4(m) x 4(n)
    const int mtile = blockIdx.y;
    const int n0    = blockIdx.x * NW;        // TABLE: col base
    const int kbase = blockIdx.x * WN;        // FUSED: k base within H

    const __nv_bfloat16* gAh = (TABLE ? g_Eh : &g_Ah[rp][0]) + (size_t)(mtile * 128) * KDIM;
    const __nv_bfloat16* gAl = (TABLE ? g_El : &g_Al[rp][0]) + (size_t)(mtile * 128) * KDIM;

    // ---- stage loader: A(hi/lo) 128x64, B(hi/lo) NWx64 ----
    auto load_stage = [&](int kc, int s) {
        const uint32_t sb = sbase + s * STAGE;
        #pragma unroll
        for (int i = 0; i < 2; i++) {
            int cid = tid + i * 512;                 // 0..1023 = 128 rows x 8 chunks
            int row = cid >> 3, ch = cid & 7;
            uint32_t so = row * 144 + ch * 16;
            const size_t ga = (size_t)row * KDIM + kc * 64 + ch * 8;
            cp_async16(sb + so,          gAh + ga);
            cp_async16(sb + ASPLIT + so, gAl + ga);
        }
        #pragma unroll
        for (int i = 0; i < NW / 64; i++) {
            int cid = tid + i * 512;                 // NW rows x 8 chunks
            int j = cid >> 3, ch = cid & 7;
            int gn;
            if (TABLE) {
                gn = n0 + j;
            } else if (FRAG) {
                int wnn = j / WN, t = j % WN, ntq = t >> 3, r8 = t & 7;
                int gate = ntq / NTG, ss = ntq % NTG;
                gn = (gate << 9) + kbase + wnn * KW + ss * 8 + r8;
            } else {
                gn = ((j / WN) << 9) + kbase + (j % WN);
            }
            const size_t gb = (size_t)gn * KTOT + KOFF + kc * 64 + ch * 8;
            cp_async16(sb + BOFF + j * 144 + ch * 16,          g_WTh + gb);
            cp_async16(sb + BOFF + BSPLIT + j * 144 + ch * 16, g_WTl + gb);
        }
    };

    float acc[2][NT][4] = {};

    #pragma unroll
    for (int s = 0; s < NSTG - 1; s++) { load_stage(s, s); CP_COMMIT(); }

    for (int c = 0; c < NC; c++) {
        if constexpr (NSTG == 3) CP_WAIT(1); else CP_WAIT(0);
        __syncthreads();
        if (c + NSTG - 1 < NC) load_stage(c + NSTG - 1, (c + NSTG - 1) % NSTG);
        CP_COMMIT();

        const uint32_t sb = sbase + (c % NSTG) * STAGE;
        #pragma unroll
        for (int k16 = 0; k16 < 4; k16++) {
            uint32_t ah[2][4], al[2][4], bfr[NT][2];
            #pragma unroll
            for (int mt = 0; mt < 2; mt++) {
                uint32_t addr = sb + (wm * 32 + mt * 16 + (lane & 15)) * 144
                              + k16 * 32 + ((lane >> 4) & 1) * 16;
                LDSM4(ah[mt], addr);
                LDSM4(al[mt], addr + ASPLIT);
            }
            // B hi
            #pragma unroll
            for (int bt = 0; bt < NT / 2; bt++) {
                int nrow = wn * WN + bt * 16 + ((lane >> 4) & 1) * 8 + (lane & 7);
                uint32_t addr = sb + BOFF + nrow * 144 + k16 * 32 + ((lane >> 3) & 1) * 16;
                uint32_t t4[4];
                LDSM4(t4, addr);
                bfr[2 * bt][0] = t4[0]; bfr[2 * bt][1] = t4[1];
                bfr[2 * bt + 1][0] = t4[2]; bfr[2 * bt + 1][1] = t4[3];
            }
            #pragma unroll
            for (int mt = 0; mt < 2; mt++)
                #pragma unroll
                for (int nt = 0; nt < NT; nt++)
                    MMA16816(acc[mt][nt], ah[mt], bfr[nt]);
            #pragma unroll
            for (int mt = 0; mt < 2; mt++)
                #pragma unroll
                for (int nt = 0; nt < NT; nt++)
                    MMA16816(acc[mt][nt], al[mt], bfr[nt]);
            // B lo (reuse regs)
            #pragma unroll
            for (int bt = 0; bt < NT / 2; bt++) {
                int nrow = wn * WN + bt * 16 + ((lane >> 4) & 1) * 8 + (lane & 7);
                uint32_t addr = sb + BOFF + BSPLIT + nrow * 144 + k16 * 32 + ((lane >> 3) & 1) * 16;
                uint32_t t4[4];
                LDSM4(t4, addr);
                bfr[2 * bt][0] = t4[0]; bfr[2 * bt][1] = t4[1];
                bfr[2 * bt + 1][0] = t4[2]; bfr[2 * bt + 1][1] = t4[3];
            }
            #pragma unroll
            for (int mt = 0; mt < 2; mt++)
                #pragma unroll
                for (int nt = 0; nt < NT; nt++)
                    MMA16816(acc[mt][nt], ah[mt], bfr[nt]);
        }
    }

    if constexpr (TABLE) {
        // direct frag store: ptab = acc + bias
        #pragma unroll
        for (int mt = 0; mt < 2; mt++) {
            #pragma unroll
            for (int nt = 0; nt < NT; nt++) {
                int col = n0 + wn * WN + nt * 8 + (lane & 3) * 2;
                int r0 = mtile * 128 + wm * 32 + mt * 16 + (lane >> 2);
                float b0 = g_bc[col], b1 = g_bc[col + 1];
                if (r0 < mrows) {
                    float2 v = make_float2(acc[mt][nt][0] + b0, acc[mt][nt][1] + b1);
                    *(float2*)&g_ptab[(size_t)r0 * COLS + col] = v;
                }
                if (r0 + 8 < mrows) {
                    float2 v = make_float2(acc[mt][nt][2] + b0, acc[mt][nt][3] + b1);
                    *(float2*)&g_ptab[(size_t)(r0 + 8) * COLS + col] = v;
                }
            }
        }
    } else if constexpr (FRAG) {
        // ---- in-register gate epilogue: c stored direct, h staged via smem ----
        __syncthreads();                         // mainloop smem reads done everywhere
        constexpr int HS = WN + 4;
        float* hbuf = (float*)smem;              // [128][HS]
        const int node1 = base + mtile * 2;      // CTA rows = pair {node1, node1+1} x 64 b
        __nv_bfloat16* wAh = &g_Ah[rp ^ 1][0];
        __nv_bfloat16* wAl = &g_Al[rp ^ 1][0];
        #pragma unroll
        for (int mt = 0; mt < 2; mt++) {
            #pragma unroll
            for (int half = 0; half < 2; half++) {
                int row = wm * 32 + mt * 16 + (lane >> 2) + half * 8;
                int b = row & 63;
                int node = node1 + (row >> 6);
                int tok = ast[b * NNODE + node];
                const float* p = g_ptab + (size_t)tok * COLS;
                size_t cch = ((size_t)(2 * node + 1) * 64 + b) * HH;  // children base
                size_t cwr = ((size_t)node * 64 + b) * HH;
                int o = half * 2;
                #pragma unroll
                for (int s = 0; s < NTG; s++) {
                    int k = kbase + wn * KW + s * 8 + (lane & 3) * 2;
                    float2 pi = *(const float2*)&p[k];
                    float2 pq = *(const float2*)&p[HH + k];
                    float2 pu = *(const float2*)&p[2 * HH + k];
                    float2 pf = *(const float2*)&p[3 * HH + k];
                    float2 ca = *(const float2*)&g_c[cch + k];
                    float2 cb = *(const float2*)&g_c[cch + (size_t)64 * HH + k];
                    float cs0 = ca.x + cb.x, cs1 = ca.y + cb.y;
                    float xi0 = acc[mt][0 * NTG + s][o]     + pi.x;
                    float xi1 = acc[mt][0 * NTG + s][o + 1] + pi.y;
                    float xo0 = acc[mt][1 * NTG + s][o]     + pq.x;
                    float xo1 = acc[mt][1 * NTG + s][o + 1] + pq.y;
                    float xu0 = acc[mt][2 * NTG + s][o]     + pu.x;
                    float xu1 = acc[mt][2 * NTG + s][o + 1] + pu.y;
                    float xf0 = acc[mt][3 * NTG + s][o]     + pf.x;
                    float xf1 = acc[mt][3 * NTG + s][o + 1] + pf.y;
                    float cc0 = fmaf(sigf(xf0), cs0, sigf(xi0) * tanhff(xu0));
                    float cc1 = fmaf(sigf(xf1), cs1, sigf(xi1) * tanhff(xu1));
                    float hh0 = sigf(xo0) * tanhff(cc0);
                    float hh1 = sigf(xo1) * tanhff(cc1);
                    *(float2*)&g_c[cwr + k] = make_float2(cc0, cc1);
                    int kl = wn * KW + s * 8 + (lane & 3) * 2;
                    *(float2*)&hbuf[row * HS + kl] = make_float2(hh0, hh1);
                }
            }
        }
        __syncthreads();
        // combine sibling h -> parent hsum split; 64*WN elems as float2 pairs
        #pragma unroll
        for (int i = 0; i < WN / 16; i++) {
            int item = tid + i * 512;            // 0..32*WN-1
            int b = item / (WN / 2), kl = (item % (WN / 2)) * 2;
            int k = kbase + kl;
            float2 h1 = *(const float2*)&hbuf[b * HS + kl];
            float2 h2 = *(const float2*)&hbuf[(b + 64) * HS + kl];
            __nv_bfloat16 hx, lx, hy, ly;
            split2(h1.x + h2.x, hx, lx);
            split2(h1.y + h2.y, hy, ly);
            size_t po = (size_t)(mtile * 64 + b) * HH + k;
            *(__nv_bfloat162*)&wAh[po] = __nv_bfloat162(hx, hy);
            *(__nv_bfloat162*)&wAl[po] = __nv_bfloat162(lx, ly);
        }
    } else {
        // ---- classic smem epilogue (NW=64: tail levels + root) ----
        __syncthreads();
        float* fbuf = (float*)smem;                  // [128][FS]
        #pragma unroll
        for (int mt = 0; mt < 2; mt++) {
            #pragma unroll
            for (int nt = 0; nt < NT; nt++) {
                int col = wn * WN + nt * 8 + (lane & 3) * 2;
                int r0 = wm * 32 + mt * 16 + (lane >> 2);
                fbuf[r0 * FS + col]           = acc[mt][nt][0];
                fbuf[r0 * FS + col + 1]       = acc[mt][nt][1];
                fbuf[(r0 + 8) * FS + col]     = acc[mt][nt][2];
                fbuf[(r0 + 8) * FS + col + 1] = acc[mt][nt][3];
            }
        }
        __syncthreads();
        if (base == 0) {
            // root: rows 0..63 valid, write out only. 64*WN elements / 512 threads.
            #pragma unroll
            for (int i = 0; i < WN / 8; i++) {
                int e = tid + i * 512;               // 0..64*WN-1
                int b = e / WN, q = e % WN;
                if (b >= 64) continue;
                int k = kbase + q;
                int tok = ast[b * NNODE];            // node 0
                const float* p = g_ptab + (size_t)tok * COLS + k;
                const float* fr = fbuf + b * FS + q;
                float xi = fr[0]      + p[0];
                float xo = fr[WN]     + p[HH];
                float xu = fr[2 * WN] + p[2 * HH];
                float xf = fr[3 * WN] + p[3 * HH];
                size_t ca = ((size_t)1 * 64 + b) * HH + k;     // children 1, 2
                float cs = g_c[ca] + g_c[ca + 64 * HH];
                float cc = fmaf(sigf(xf), cs, sigf(xi) * tanhff(xu));
                out[(size_t)b * HH + k] = sigf(xo) * tanhff(cc);
            }
        } else {
            const int node1 = base + mtile * 2;      // odd = 2p+1; sibling node1+1
            __nv_bfloat16* wAh = &g_Ah[rp ^ 1][0];
            __nv_bfloat16* wAl = &g_Al[rp ^ 1][0];
            #pragma unroll
            for (int i = 0; i < WN / 8; i++) {
                int e = tid + i * 512;               // 0..64*WN-1
                int b = e / WN, q = e % WN;
                int k = kbase + q;
                int tok1 = ast[b * NNODE + node1];
                int tok2 = ast[b * NNODE + node1 + 1];
                const float* p1 = g_ptab + (size_t)tok1 * COLS + k;
                const float* p2 = g_ptab + (size_t)tok2 * COLS + k;
                const float* f1 = fbuf + b * FS + q;
                const float* f2 = fbuf + (b + 64) * FS + q;
                size_t ca = ((size_t)(2 * node1 + 1) * 64 + b) * HH + k;
                float cs1 = g_c[ca] + g_c[ca + 64 * HH];
                size_t cb = ((size_t)(2 * node1 + 3) * 64 + b) * HH + k;
                float cs2 = g_c[cb] + g_c[cb + 64 * HH];
                float cc1 = fmaf(sigf(f1[3 * WN] + p1[3 * HH]), cs1,
                                 sigf(f1[0] + p1[0]) * tanhff(f1[2 * WN] + p1[2 * HH]));
                float hh1 = sigf(f1[WN] + p1[HH]) * tanhff(cc1);
                float cc2 = fmaf(sigf(f2[3 * WN] + p2[3 * HH]), cs2,
                                 sigf(f2[0] + p2[0]) * tanhff(f2[2 * WN] + p2[2 * HH]));
                float hh2 = sigf(f2[WN] + p2[HH]) * tanhff(cc2);
                size_t gi1 = ((size_t)node1 * 64 + b) * HH + k;
                g_c[gi1] = cc1;
                g_c[gi1 + 64 * HH] = cc2;
                __nv_bfloat16 hi, lo; split2(hh1 + hh2, hi, lo);
                size_t po = (size_t)(mtile * 64 + b) * HH + k;   // parent local row
                wAh[po] = hi;
                wAl[po] = lo;
            }
        }
    }
}

// ---------------- launch ----------------
extern "C" void kernel_launch(void* const* d_in, const int* in_sizes, int n_in,
                              void* d_out, int out_size) {
    const int*   ast   = (const int*)d_in[0];
    // d_in[1] = parent (structurally (i-1)/2, unused)
    const float* emb   = (const float*)d_in[2];
    const float* W_iou = (const float*)d_in[3];
    const float* b_iou = (const float*)d_in[4];
    const float* W_f   = (const float*)d_in[5];
    const float* b_f   = (const float*)d_in[6];
    float* out = (float*)d_out;
    (void)in_sizes; (void)n_in; (void)out_size;

    constexpr int SMEM64  = (36864 + 2 * 64 * 144) * 3;    // 165888
    constexpr int SMEM128 = (36864 + 2 * 128 * 144) * 3;   // 221184
    constexpr int SMEM256 = (36864 + 2 * 256 * 144) * 2;   // 221184
    cudaFuncSetAttribute(mma_gemm<EE, true, 128>,  cudaFuncAttributeMaxDynamicSharedMemorySize, SMEM128);
    cudaFuncSetAttribute(mma_gemm<HH, false, 64>,  cudaFuncAttributeMaxDynamicSharedMemorySize, SMEM64);
    cudaFuncSetAttribute(mma_gemm<HH, false, 128>, cudaFuncAttributeMaxDynamicSharedMemorySize, SMEM128);
    cudaFuncSetAttribute(mma_gemm<HH, false, 256>, cudaFuncAttributeMaxDynamicSharedMemorySize, SMEM256);

    packT_kernel<<<dim3(COLS / 32, KTOT / 32), dim3(32, 8)>>>(W_iou, W_f);
    esplit_kernel<<<(2048 * EE + 255) / 256, 256>>>(emb, b_iou, b_f);

    // ptab = emb_table @ Wx + bias : M=2000 (pad 2048), K=256, N=2048
    {
        dim3 grid(COLS / 128, 16);
        mma_gemm<EE, true, 128><<<grid, 512, SMEM128>>>(nullptr, 0, VOCAB, nullptr, 0);
    }

    // leaves: gates + parent hsum-split into buf 0
    leaf_gate<<<(256 * 64 * (HH / 4) + 255) / 256, 256>>>(ast);

    // levels 8..0: fused GEMM + gates + next-level hsum-split
    for (int d = 8; d >= 0; d--) {
        int L = 1 << d;
        int base = L - 1;
        int M = 64 * L;
        int mtiles = (M + 127) / 128;
        if (d >= 5) {
            dim3 grid(HH / 64, mtiles);
            mma_gemm<HH, false, 256><<<grid, 512, SMEM256>>>(ast, base, M, nullptr, d & 1);
        } else if (d == 4) {
            dim3 grid(HH / 32, mtiles);
            mma_gemm<HH, false, 128><<<grid, 512, SMEM128>>>(ast, base, M, nullptr, d & 1);
        } else {
            dim3 grid(HH / 16, mtiles);
            mma_gemm<HH, false, 64><<<grid, 512, SMEM64>>>(ast, base, M, (d == 0) ? out : nullptr, d & 1);
        }
    }
}

// round 14
// speedup vs baseline: 1.0254x; 1.0254x over previous
#include <cuda_runtime.h>
#include <cuda_bf16.h>
#include <cstdint>
#include <cstddef>

// ---------------- problem constants ----------------
#define BB    64
#define NNODE 1023
#define EE    256
#define HH    512
#define COLS  2048      // 4*H gate columns [i|o|u|f]
#define KTOT  768       // E + H
#define VOCAB 2000
#define MAXMR 16384     // max rows in a recurrent level (level 8: 256*64)

// ---------------- device scratch (allocation-free) ----------------
__device__ __nv_bfloat16 g_WTh[(size_t)COLS * KTOT];   // W^T hi  [n][k]
__device__ __nv_bfloat16 g_WTl[(size_t)COLS * KTOT];   // W^T lo
__device__ float         g_bc[COLS];                   // packed bias
__device__ __nv_bfloat16 g_Eh[2048 * EE];              // emb_table split (padded to 2048 rows)
__device__ __nv_bfloat16 g_El[2048 * EE];
__device__ float         g_ptab[(size_t)VOCAB * COLS]; // emb_table @ Wx + bias
__device__ __nv_bfloat16 g_Ah[2][(size_t)MAXMR * HH];  // hsum split, double-buffered by level parity
__device__ __nv_bfloat16 g_Al[2][(size_t)MAXMR * HH];
__device__ float         g_c[(size_t)BB * NNODE * HH];

// ---------------- helpers ----------------
__device__ __forceinline__ uint32_t smem_u32(const void* p) {
    uint32_t a;
    asm("{ .reg .u64 t; cvta.to.shared.u64 t, %1; cvt.u32.u64 %0, t; }" : "=r"(a) : "l"(p));
    return a;
}
__device__ __forceinline__ void cp_async16(uint32_t saddr, const void* g) {
    asm volatile("cp.async.cg.shared.global [%0], [%1], 16;"
                 :: "r"(saddr), "l"(__cvta_generic_to_global(g)) : "memory");
}
#define CP_COMMIT() asm volatile("cp.async.commit_group;" ::: "memory")
#define CP_WAIT(n)  asm volatile("cp.async.wait_group %0;" :: "n"(n) : "memory")

#define LDSM4(r, addr) \
    asm volatile("ldmatrix.sync.aligned.m8n8.x4.shared.b16 {%0,%1,%2,%3}, [%4];" \
        : "=r"((r)[0]), "=r"((r)[1]), "=r"((r)[2]), "=r"((r)[3]) : "r"(addr))

#define MMA16816(d, a, b) \
    asm volatile("mma.sync.aligned.m16n8k16.row.col.f32.bf16.bf16.f32 " \
        "{%0,%1,%2,%3}, {%4,%5,%6,%7}, {%8,%9}, {%0,%1,%2,%3};" \
        : "+f"((d)[0]), "+f"((d)[1]), "+f"((d)[2]), "+f"((d)[3]) \
        : "r"((a)[0]), "r"((a)[1]), "r"((a)[2]), "r"((a)[3]), "r"((b)[0]), "r"((b)[1]))

__device__ __forceinline__ void split2(float v, __nv_bfloat16& hi, __nv_bfloat16& lo) {
    hi = __float2bfloat16(v);
    lo = __float2bfloat16(v - __bfloat162float(hi));
}
// fast gates (MUFU-based): ~1e-7 rel error
__device__ __forceinline__ float sigf(float x)  { return __fdividef(1.f, 1.f + __expf(-x)); }
__device__ __forceinline__ float tanhff(float x){ return __fdividef(2.f, 1.f + __expf(-2.f * x)) - 1.f; }

// ---------------- coalesced transpose pack of W^T hi/lo ----------------
__global__ void packT_kernel(const float* __restrict__ W_iou, const float* __restrict__ W_f) {
    __shared__ float tile[32][33];
    int n0 = blockIdx.x * 32, k0 = blockIdx.y * 32;
    int tx = threadIdx.x, ty = threadIdx.y;      // (32, 8)
    #pragma unroll
    for (int j = 0; j < 4; j++) {
        int k = k0 + ty + j * 8;
        int n = n0 + tx;
        float w = (n < 3 * HH) ? W_iou[k * (3 * HH) + n] : W_f[k * HH + (n - 3 * HH)];
        tile[ty + j * 8][tx] = w;
    }
    __syncthreads();
    #pragma unroll
    for (int j = 0; j < 4; j++) {
        int n = n0 + ty + j * 8;
        int k = k0 + tx;
        float w = tile[tx][ty + j * 8];
        __nv_bfloat16 hi, lo; split2(w, hi, lo);
        g_WTh[(size_t)n * KTOT + k] = hi;
        g_WTl[(size_t)n * KTOT + k] = lo;
    }
}

// ---------------- split emb table (pad to 2048 rows) + bias pack ----------------
__global__ void esplit_kernel(const float* __restrict__ emb,
                              const float* __restrict__ b_iou, const float* __restrict__ b_f) {
    int idx = blockIdx.x * blockDim.x + threadIdx.x;   // over 2048*256
    if (idx >= 2048 * EE) return;
    int r = idx >> 8, k = idx & 255;
    float v = (r < VOCAB) ? emb[r * EE + k] : 0.f;
    __nv_bfloat16 hi, lo; split2(v, hi, lo);
    g_Eh[idx] = hi; g_El[idx] = lo;
    if (idx < COLS)
        g_bc[idx] = (idx < 3 * HH) ? b_iou[idx] : b_f[idx - 3 * HH];
}

// ---------------- leaf gates over sibling pairs (8 k's per thread) ----------------
__global__ void leaf_gate(const int* __restrict__ ast) {
    int idx = blockIdx.x * blockDim.x + threadIdx.x;   // over 256*64*64
    if (idx >= 256 * 64 * (HH / 8)) return;
    int k = (idx & 63) * 8;
    int t = idx >> 6;                                  // pair*64 + b
    int b = t & 63, pr = t >> 6;                       // pair 0..255
    int n1 = 511 + 2 * pr;                             // odd leaf of the pair
    int tok1 = ast[b * NNODE + n1];
    int tok2 = ast[b * NNODE + n1 + 1];
    const float* p1 = g_ptab + (size_t)tok1 * COLS + k;
    const float* p2 = g_ptab + (size_t)tok2 * COLS + k;
    size_t gi1 = ((size_t)n1 * 64 + b) * HH + k;
    size_t po = (size_t)(pr * 64 + b) * HH + k;        // parent local row at level 8
    __nv_bfloat16 hsp[8], lsp[8];
    #pragma unroll
    for (int half = 0; half < 2; half++) {
        int o = half * 4;
        float4 i1 = *(const float4*)&p1[o],          i2 = *(const float4*)&p2[o];
        float4 o1 = *(const float4*)&p1[HH + o],     o2 = *(const float4*)&p2[HH + o];
        float4 u1 = *(const float4*)&p1[2 * HH + o], u2 = *(const float4*)&p2[2 * HH + o];
        float4 c1, c2, hs;
        c1.x = sigf(i1.x) * tanhff(u1.x);  c2.x = sigf(i2.x) * tanhff(u2.x);
        c1.y = sigf(i1.y) * tanhff(u1.y);  c2.y = sigf(i2.y) * tanhff(u2.y);
        c1.z = sigf(i1.z) * tanhff(u1.z);  c2.z = sigf(i2.z) * tanhff(u2.z);
        c1.w = sigf(i1.w) * tanhff(u1.w);  c2.w = sigf(i2.w) * tanhff(u2.w);
        hs.x = sigf(o1.x) * tanhff(c1.x) + sigf(o2.x) * tanhff(c2.x);
        hs.y = sigf(o1.y) * tanhff(c1.y) + sigf(o2.y) * tanhff(c2.y);
        hs.z = sigf(o1.z) * tanhff(c1.z) + sigf(o2.z) * tanhff(c2.z);
        hs.w = sigf(o1.w) * tanhff(c1.w) + sigf(o2.w) * tanhff(c2.w);
        *(float4*)&g_c[gi1 + o] = c1;
        *(float4*)&g_c[gi1 + 64 * HH + o] = c2;
        split2(hs.x, hsp[o], lsp[o]);     split2(hs.y, hsp[o + 1], lsp[o + 1]);
        split2(hs.z, hsp[o + 2], lsp[o + 2]); split2(hs.w, hsp[o + 3], lsp[o + 3]);
    }
    *(uint4*)&g_Ah[0][po] = *(uint4*)hsp;
    *(uint4*)&g_Al[0][po] = *(uint4*)lsp;
}

// ---------------- bf16x3 mma.sync GEMM: 512 thr, 4x4 warps, CTA 128 x NW ----------------
// K consumed in 64-wide chunks (144B-stride smem rows; 4 k16 sub-steps per chunk).
// NW=64/128: 3-stage;  NW=256: 2-stage
// TABLE=true : g_ptab = Eh/El @ W[0:256] + bias                         (K=256)
// TABLE=false: fused: act = ptab[tok] + hsum@W[256:768]; gates -> c, parent hsum-split
//              CTA covers WN k-values x 4 gates; rows = one sibling pair x 64 batches
template <int KDIM, bool TABLE, int NW>
__global__ __launch_bounds__(512, 1)
void mma_gemm(const int* __restrict__ ast, int base, int mrows, float* __restrict__ out, int rp) {
    constexpr int WN     = NW / 4;            // warp n-width: 16 / 32 / 64
    constexpr int NT     = WN / 8;            // n-subtiles per warp: 2 / 4 / 8
    constexpr int ASPLIT = 128 * 144;         // 18432 bytes per A split
    constexpr int BOFF   = 2 * ASPLIT;        // 36864
    constexpr int BSPLIT = NW * 144;          // bytes per B split
    constexpr int STAGE  = BOFF + 2 * BSPLIT;
    constexpr int NSTG   = (NW >= 256) ? 2 : 3;
    constexpr int FS     = NW + NW / 32;      // fbuf row stride
    constexpr int NC     = KDIM / 64;
    constexpr int KOFF   = TABLE ? 0 : EE;

    extern __shared__ char smem[];
    const uint32_t sbase = smem_u32(smem);
    const int tid = threadIdx.x;
    const int lane = tid & 31, wid = tid >> 5;
    const int wm = wid >> 2, wn = wid & 3;    // warp grid 4(m) x 4(n)
    const int mtile = blockIdx.y;
    const int n0    = blockIdx.x * NW;        // TABLE: col base
    const int kbase = blockIdx.x * WN;        // FUSED: k base within H

    const __nv_bfloat16* gAh = (TABLE ? g_Eh : &g_Ah[rp][0]) + (size_t)(mtile * 128) * KDIM;
    const __nv_bfloat16* gAl = (TABLE ? g_El : &g_Al[rp][0]) + (size_t)(mtile * 128) * KDIM;

    // ---- stage loader: A(hi/lo) 128x64, B(hi/lo) NWx64 ----
    auto load_stage = [&](int kc, int s) {
        const uint32_t sb = sbase + s * STAGE;
        #pragma unroll
        for (int i = 0; i < 2; i++) {
            int cid = tid + i * 512;                 // 0..1023 = 128 rows x 8 chunks
            int row = cid >> 3, ch = cid & 7;
            uint32_t so = row * 144 + ch * 16;
            const size_t ga = (size_t)row * KDIM + kc * 64 + ch * 8;
            cp_async16(sb + so,          gAh + ga);
            cp_async16(sb + ASPLIT + so, gAl + ga);
        }
        #pragma unroll
        for (int i = 0; i < NW / 64; i++) {
            int cid = tid + i * 512;                 // NW rows x 8 chunks
            int j = cid >> 3, ch = cid & 7;
            int gn = TABLE ? (n0 + j) : (((j / WN) << 9) + kbase + (j % WN));
            const size_t gb = (size_t)gn * KTOT + KOFF + kc * 64 + ch * 8;
            cp_async16(sb + BOFF + j * 144 + ch * 16,          g_WTh + gb);
            cp_async16(sb + BOFF + BSPLIT + j * 144 + ch * 16, g_WTl + gb);
        }
    };

    float acc[2][NT][4] = {};

    #pragma unroll
    for (int s = 0; s < NSTG - 1; s++) { load_stage(s, s); CP_COMMIT(); }

    for (int c = 0; c < NC; c++) {
        if constexpr (NSTG == 3) CP_WAIT(1); else CP_WAIT(0);
        __syncthreads();
        if (c + NSTG - 1 < NC) load_stage(c + NSTG - 1, (c + NSTG - 1) % NSTG);
        CP_COMMIT();

        const uint32_t sb = sbase + (c % NSTG) * STAGE;
        #pragma unroll
        for (int k16 = 0; k16 < 4; k16++) {
            uint32_t ah[2][4], al[2][4], bfr[NT][2];
            #pragma unroll
            for (int mt = 0; mt < 2; mt++) {
                uint32_t addr = sb + (wm * 32 + mt * 16 + (lane & 15)) * 144
                              + k16 * 32 + ((lane >> 4) & 1) * 16;
                LDSM4(ah[mt], addr);
                LDSM4(al[mt], addr + ASPLIT);
            }
            // B hi
            #pragma unroll
            for (int bt = 0; bt < NT / 2; bt++) {
                int nrow = wn * WN + bt * 16 + ((lane >> 4) & 1) * 8 + (lane & 7);
                uint32_t addr = sb + BOFF + nrow * 144 + k16 * 32 + ((lane >> 3) & 1) * 16;
                uint32_t t4[4];
                LDSM4(t4, addr);
                bfr[2 * bt][0] = t4[0]; bfr[2 * bt][1] = t4[1];
                bfr[2 * bt + 1][0] = t4[2]; bfr[2 * bt + 1][1] = t4[3];
            }
            #pragma unroll
            for (int mt = 0; mt < 2; mt++)
                #pragma unroll
                for (int nt = 0; nt < NT; nt++)
                    MMA16816(acc[mt][nt], ah[mt], bfr[nt]);
            #pragma unroll
            for (int mt = 0; mt < 2; mt++)
                #pragma unroll
                for (int nt = 0; nt < NT; nt++)
                    MMA16816(acc[mt][nt], al[mt], bfr[nt]);
            // B lo (reuse regs)
            #pragma unroll
            for (int bt = 0; bt < NT / 2; bt++) {
                int nrow = wn * WN + bt * 16 + ((lane >> 4) & 1) * 8 + (lane & 7);
                uint32_t addr = sb + BOFF + BSPLIT + nrow * 144 + k16 * 32 + ((lane >> 3) & 1) * 16;
                uint32_t t4[4];
                LDSM4(t4, addr);
                bfr[2 * bt][0] = t4[0]; bfr[2 * bt][1] = t4[1];
                bfr[2 * bt + 1][0] = t4[2]; bfr[2 * bt + 1][1] = t4[3];
            }
            #pragma unroll
            for (int mt = 0; mt < 2; mt++)
                #pragma unroll
                for (int nt = 0; nt < NT; nt++)
                    MMA16816(acc[mt][nt], ah[mt], bfr[nt]);
        }
    }

    if constexpr (TABLE) {
        // direct frag store: ptab = acc + bias
        #pragma unroll
        for (int mt = 0; mt < 2; mt++) {
            #pragma unroll
            for (int nt = 0; nt < NT; nt++) {
                int col = n0 + wn * WN + nt * 8 + (lane & 3) * 2;
                int r0 = mtile * 128 + wm * 32 + mt * 16 + (lane >> 2);
                float b0 = g_bc[col], b1 = g_bc[col + 1];
                if (r0 < mrows) {
                    float2 v = make_float2(acc[mt][nt][0] + b0, acc[mt][nt][1] + b1);
                    *(float2*)&g_ptab[(size_t)r0 * COLS + col] = v;
                }
                if (r0 + 8 < mrows) {
                    float2 v = make_float2(acc[mt][nt][2] + b0, acc[mt][nt][3] + b1);
                    *(float2*)&g_ptab[(size_t)(r0 + 8) * COLS + col] = v;
                }
            }
        }
    } else {
        // stage acc -> smem, then fused gate + hsum-split epilogue
        __syncthreads();
        float* fbuf = (float*)smem;                  // [128][FS]
        #pragma unroll
        for (int mt = 0; mt < 2; mt++) {
            #pragma unroll
            for (int nt = 0; nt < NT; nt++) {
                int col = wn * WN + nt * 8 + (lane & 3) * 2;
                int r0 = wm * 32 + mt * 16 + (lane >> 2);
                fbuf[r0 * FS + col]           = acc[mt][nt][0];
                fbuf[r0 * FS + col + 1]       = acc[mt][nt][1];
                fbuf[(r0 + 8) * FS + col]     = acc[mt][nt][2];
                fbuf[(r0 + 8) * FS + col + 1] = acc[mt][nt][3];
            }
        }
        __syncthreads();
        if (base == 0) {
            // root: rows 0..63 valid, write out only. 64*WN elements / 512 threads.
            #pragma unroll
            for (int i = 0; i < WN / 8; i++) {
                int e = tid + i * 512;               // 0..64*WN-1
                int b = e / WN, q = e % WN;
                if (b >= 64) continue;
                int k = kbase + q;
                int tok = ast[b * NNODE];            // node 0
                const float* p = g_ptab + (size_t)tok * COLS + k;
                const float* fr = fbuf + b * FS + q;
                float xi = fr[0]      + p[0];
                float xo = fr[WN]     + p[HH];
                float xu = fr[2 * WN] + p[2 * HH];
                float xf = fr[3 * WN] + p[3 * HH];
                size_t ca = ((size_t)1 * 64 + b) * HH + k;     // children 1, 2
                float cs = g_c[ca] + g_c[ca + 64 * HH];
                float cc = fmaf(sigf(xf), cs, sigf(xi) * tanhff(xu));
                out[(size_t)b * HH + k] = sigf(xo) * tanhff(cc);
            }
        } else {
            const int node1 = base + mtile * 2;      // odd = 2p+1; sibling node1+1
            __nv_bfloat16* wAh = &g_Ah[rp ^ 1][0];
            __nv_bfloat16* wAl = &g_Al[rp ^ 1][0];
            #pragma unroll
            for (int i = 0; i < WN / 8; i++) {
                int e = tid + i * 512;               // 0..64*WN-1
                int b = e / WN, q = e % WN;
                int k = kbase + q;
                int tok1 = ast[b * NNODE + node1];
                int tok2 = ast[b * NNODE + node1 + 1];
                const float* p1 = g_ptab + (size_t)tok1 * COLS + k;
                const float* p2 = g_ptab + (size_t)tok2 * COLS + k;
                const float* f1 = fbuf + b * FS + q;
                const float* f2 = fbuf + (b + 64) * FS + q;
                size_t ca = ((size_t)(2 * node1 + 1) * 64 + b) * HH + k;
                float cs1 = g_c[ca] + g_c[ca + 64 * HH];
                size_t cb = ((size_t)(2 * node1 + 3) * 64 + b) * HH + k;
                float cs2 = g_c[cb] + g_c[cb + 64 * HH];
                float cc1 = fmaf(sigf(f1[3 * WN] + p1[3 * HH]), cs1,
                                 sigf(f1[0] + p1[0]) * tanhff(f1[2 * WN] + p1[2 * HH]));
                float hh1 = sigf(f1[WN] + p1[HH]) * tanhff(cc1);
                float cc2 = fmaf(sigf(f2[3 * WN] + p2[3 * HH]), cs2,
                                 sigf(f2[0] + p2[0]) * tanhff(f2[2 * WN] + p2[2 * HH]));
                float hh2 = sigf(f2[WN] + p2[HH]) * tanhff(cc2);
                size_t gi1 = ((size_t)node1 * 64 + b) * HH + k;
                g_c[gi1] = cc1;
                g_c[gi1 + 64 * HH] = cc2;
                __nv_bfloat16 hi, lo; split2(hh1 + hh2, hi, lo);
                size_t po = (size_t)(mtile * 64 + b) * HH + k;   // parent local row
                wAh[po] = hi;
                wAl[po] = lo;
            }
        }
    }
}

// ---------------- launch ----------------
extern "C" void kernel_launch(void* const* d_in, const int* in_sizes, int n_in,
                              void* d_out, int out_size) {
    const int*   ast   = (const int*)d_in[0];
    // d_in[1] = parent (structurally (i-1)/2, unused)
    const float* emb   = (const float*)d_in[2];
    const float* W_iou = (const float*)d_in[3];
    const float* b_iou = (const float*)d_in[4];
    const float* W_f   = (const float*)d_in[5];
    const float* b_f   = (const float*)d_in[6];
    float* out = (float*)d_out;
    (void)in_sizes; (void)n_in; (void)out_size;

    constexpr int SMEM64  = (36864 + 2 * 64 * 144) * 3;    // 165888
    constexpr int SMEM128 = (36864 + 2 * 128 * 144) * 3;   // 221184
    constexpr int SMEM256 = (36864 + 2 * 256 * 144) * 2;   // 221184
    cudaFuncSetAttribute(mma_gemm<EE, true, 128>,  cudaFuncAttributeMaxDynamicSharedMemorySize, SMEM128);
    cudaFuncSetAttribute(mma_gemm<HH, false, 64>,  cudaFuncAttributeMaxDynamicSharedMemorySize, SMEM64);
    cudaFuncSetAttribute(mma_gemm<HH, false, 128>, cudaFuncAttributeMaxDynamicSharedMemorySize, SMEM128);
    cudaFuncSetAttribute(mma_gemm<HH, false, 256>, cudaFuncAttributeMaxDynamicSharedMemorySize, SMEM256);

    packT_kernel<<<dim3(COLS / 32, KTOT / 32), dim3(32, 8)>>>(W_iou, W_f);
    esplit_kernel<<<(2048 * EE + 255) / 256, 256>>>(emb, b_iou, b_f);

    // ptab = emb_table @ Wx + bias : M=2000 (pad 2048), K=256, N=2048
    {
        dim3 grid(COLS / 128, 16);
        mma_gemm<EE, true, 128><<<grid, 512, SMEM128>>>(nullptr, 0, VOCAB, nullptr, 0);
    }

    // leaves: gates + parent hsum-split into buf 0
    leaf_gate<<<(256 * 64 * (HH / 8) + 255) / 256, 256>>>(ast);

    // levels 8..0: fused GEMM + gates + next-level hsum-split
    for (int d = 8; d >= 0; d--) {
        int L = 1 << d;
        int base = L - 1;
        int M = 64 * L;
        int mtiles = (M + 127) / 128;
        if (d >= 5) {
            dim3 grid(HH / 64, mtiles);
            mma_gemm<HH, false, 256><<<grid, 512, SMEM256>>>(ast, base, M, nullptr, d & 1);
        } else if (d == 4) {
            dim3 grid(HH / 32, mtiles);
            mma_gemm<HH, false, 128><<<grid, 512, SMEM128>>>(ast, base, M, nullptr, d & 1);
        } else {
            dim3 grid(HH / 16, mtiles);
            mma_gemm<HH, false, 64><<<grid, 512, SMEM64>>>(ast, base, M, (d == 0) ? out : nullptr, d & 1);
        }
    }
}

// round 17
// speedup vs baseline: 1.0340x; 1.0084x over previous
#include <cuda_runtime.h>
#include <cuda_bf16.h>
#include <cstdint>
#include <cstddef>

// ---------------- problem constants ----------------
#define BB    64
#define NNODE 1023
#define EE    256
#define HH    512
#define COLS  2048      // 4*H gate columns [i|o|u|f]
#define KTOT  768       // E + H
#define VOCAB 2000
#define MAXMR 16384     // max rows in a recurrent level (level 8: 256*64)

// ---------------- device scratch (allocation-free) ----------------
__device__ __nv_bfloat16 g_WTh[(size_t)COLS * KTOT];   // W^T hi  [n][k]
__device__ __nv_bfloat16 g_WTl[(size_t)COLS * KTOT];   // W^T lo
__device__ float         g_bc[COLS];                   // packed bias
__device__ __nv_bfloat16 g_Eh[2048 * EE];              // emb_table split (padded to 2048 rows)
__device__ __nv_bfloat16 g_El[2048 * EE];
__device__ float         g_ptab[(size_t)VOCAB * COLS]; // emb_table @ Wx + bias
__device__ __nv_bfloat16 g_Ah[2][(size_t)MAXMR * HH];  // hsum split, double-buffered by level parity
__device__ __nv_bfloat16 g_Al[2][(size_t)MAXMR * HH];
__device__ float         g_c[(size_t)BB * NNODE * HH];

// ---------------- helpers ----------------
__device__ __forceinline__ uint32_t smem_u32(const void* p) {
    uint32_t a;
    asm("{ .reg .u64 t; cvta.to.shared.u64 t, %1; cvt.u32.u64 %0, t; }" : "=r"(a) : "l"(p));
    return a;
}
__device__ __forceinline__ void cp_async16(uint32_t saddr, const void* g) {
    asm volatile("cp.async.cg.shared.global [%0], [%1], 16;"
                 :: "r"(saddr), "l"(__cvta_generic_to_global(g)) : "memory");
}
#define CP_COMMIT() asm volatile("cp.async.commit_group;" ::: "memory")
#define CP_WAIT(n)  asm volatile("cp.async.wait_group %0;" :: "n"(n) : "memory")

#define LDSM4(r, addr) \
    asm volatile("ldmatrix.sync.aligned.m8n8.x4.shared.b16 {%0,%1,%2,%3}, [%4];" \
        : "=r"((r)[0]), "=r"((r)[1]), "=r"((r)[2]), "=r"((r)[3]) : "r"(addr))

#define MMA16816(d, a, b) \
    asm volatile("mma.sync.aligned.m16n8k16.row.col.f32.bf16.bf16.f32 " \
        "{%0,%1,%2,%3}, {%4,%5,%6,%7}, {%8,%9}, {%0,%1,%2,%3};" \
        : "+f"((d)[0]), "+f"((d)[1]), "+f"((d)[2]), "+f"((d)[3]) \
        : "r"((a)[0]), "r"((a)[1]), "r"((a)[2]), "r"((a)[3]), "r"((b)[0]), "r"((b)[1]))

__device__ __forceinline__ void split2(float v, __nv_bfloat16& hi, __nv_bfloat16& lo) {
    hi = __float2bfloat16(v);
    lo = __float2bfloat16(v - __bfloat162float(hi));
}
// fast gates (MUFU-based): ~1e-7 rel error
__device__ __forceinline__ float sigf(float x)  { return __fdividef(1.f, 1.f + __expf(-x)); }
__device__ __forceinline__ float tanhff(float x){ return __fdividef(2.f, 1.f + __expf(-2.f * x)) - 1.f; }

// ---------------- coalesced transpose pack of W^T hi/lo ----------------
__global__ void packT_kernel(const float* __restrict__ W_iou, const float* __restrict__ W_f) {
    __shared__ float tile[32][33];
    int n0 = blockIdx.x * 32, k0 = blockIdx.y * 32;
    int tx = threadIdx.x, ty = threadIdx.y;      // (32, 8)
    #pragma unroll
    for (int j = 0; j < 4; j++) {
        int k = k0 + ty + j * 8;
        int n = n0 + tx;
        float w = (n < 3 * HH) ? W_iou[k * (3 * HH) + n] : W_f[k * HH + (n - 3 * HH)];
        tile[ty + j * 8][tx] = w;
    }
    __syncthreads();
    #pragma unroll
    for (int j = 0; j < 4; j++) {
        int n = n0 + ty + j * 8;
        int k = k0 + tx;
        float w = tile[tx][ty + j * 8];
        __nv_bfloat16 hi, lo; split2(w, hi, lo);
        g_WTh[(size_t)n * KTOT + k] = hi;
        g_WTl[(size_t)n * KTOT + k] = lo;
    }
}

// ---------------- split emb table (pad to 2048 rows) + bias pack ----------------
__global__ void esplit_kernel(const float* __restrict__ emb,
                              const float* __restrict__ b_iou, const float* __restrict__ b_f) {
    int idx = blockIdx.x * blockDim.x + threadIdx.x;   // over 2048*256
    if (idx >= 2048 * EE) return;
    int r = idx >> 8, k = idx & 255;
    float v = (r < VOCAB) ? emb[r * EE + k] : 0.f;
    __nv_bfloat16 hi, lo; split2(v, hi, lo);
    g_Eh[idx] = hi; g_El[idx] = lo;
    if (idx < COLS)
        g_bc[idx] = (idx < 3 * HH) ? b_iou[idx] : b_f[idx - 3 * HH];
}

// ---------------- leaf gates over sibling pairs (float4 over k) ----------------
__global__ void leaf_gate(const int* __restrict__ ast) {
    int idx = blockIdx.x * blockDim.x + threadIdx.x;   // over 256*64*128
    if (idx >= 256 * 64 * (HH / 4)) return;
    int k = (idx & 127) * 4;
    int t = idx >> 7;                                  // pair*64 + b
    int b = t & 63, pr = t >> 6;                       // pair 0..255
    int n1 = 511 + 2 * pr;                             // odd leaf of the pair
    int tok1 = ast[b * NNODE + n1];
    int tok2 = ast[b * NNODE + n1 + 1];
    const float* p1 = g_ptab + (size_t)tok1 * COLS + k;
    const float* p2 = g_ptab + (size_t)tok2 * COLS + k;
    float4 i1 = *(const float4*)&p1[0],      i2 = *(const float4*)&p2[0];
    float4 o1 = *(const float4*)&p1[HH],     o2 = *(const float4*)&p2[HH];
    float4 u1 = *(const float4*)&p1[2 * HH], u2 = *(const float4*)&p2[2 * HH];
    float4 c1, c2, hs;
    c1.x = sigf(i1.x) * tanhff(u1.x);  c2.x = sigf(i2.x) * tanhff(u2.x);
    c1.y = sigf(i1.y) * tanhff(u1.y);  c2.y = sigf(i2.y) * tanhff(u2.y);
    c1.z = sigf(i1.z) * tanhff(u1.z);  c2.z = sigf(i2.z) * tanhff(u2.z);
    c1.w = sigf(i1.w) * tanhff(u1.w);  c2.w = sigf(i2.w) * tanhff(u2.w);
    hs.x = sigf(o1.x) * tanhff(c1.x) + sigf(o2.x) * tanhff(c2.x);
    hs.y = sigf(o1.y) * tanhff(c1.y) + sigf(o2.y) * tanhff(c2.y);
    hs.z = sigf(o1.z) * tanhff(c1.z) + sigf(o2.z) * tanhff(c2.z);
    hs.w = sigf(o1.w) * tanhff(c1.w) + sigf(o2.w) * tanhff(c2.w);
    size_t gi1 = ((size_t)n1 * 64 + b) * HH + k;
    *(float4*)&g_c[gi1] = c1;
    *(float4*)&g_c[gi1 + 64 * HH] = c2;
    __nv_bfloat16 h0, l0, h1, l1, h2, l2, h3, l3;
    split2(hs.x, h0, l0); split2(hs.y, h1, l1);
    split2(hs.z, h2, l2); split2(hs.w, h3, l3);
    size_t po = (size_t)(pr * 64 + b) * HH + k;        // parent local row at level 8
    __nv_bfloat162 hh[2] = {__nv_bfloat162(h0, h1), __nv_bfloat162(h2, h3)};
    __nv_bfloat162 ll[2] = {__nv_bfloat162(l0, l1), __nv_bfloat162(l2, l3)};
    *(uint2*)&g_Ah[0][po] = *(uint2*)hh;
    *(uint2*)&g_Al[0][po] = *(uint2*)ll;
}

// ---------------- bf16x3 mma.sync GEMM: 512 thr, 4x4 warps, CTA 128 x NW ----------------
// K consumed in 64-wide chunks (144B-stride smem rows; 4 k16 sub-steps per chunk).
// NW=64/128: 3-stage;  NW=256: 2-stage
// Pipeline order (R12, proven): CP_WAIT -> __syncthreads (visibility + stage reuse)
//   -> issue next loads -> commit -> compute. Do NOT reorder the wait after the
//   load-issue: cp.async visibility to OTHER threads requires barrier AFTER wait.
// TABLE=true : g_ptab = Eh/El @ W[0:256] + bias                         (K=256)
// TABLE=false: fused: act = ptab[tok] + hsum@W[256:768]; gates -> c, parent hsum-split
//              CTA covers WN k-values x 4 gates; rows = one sibling pair x 64 batches
template <int KDIM, bool TABLE, int NW>
__global__ __launch_bounds__(512, 1)
void mma_gemm(const int* __restrict__ ast, int base, int mrows, float* __restrict__ out, int rp) {
    constexpr int WN     = NW / 4;            // warp n-width: 16 / 32 / 64
    constexpr int NT     = WN / 8;            // n-subtiles per warp: 2 / 4 / 8
    constexpr int ASPLIT = 128 * 144;         // 18432 bytes per A split
    constexpr int BOFF   = 2 * ASPLIT;        // 36864
    constexpr int BSPLIT = NW * 144;          // bytes per B split
    constexpr int STAGE  = BOFF + 2 * BSPLIT;
    constexpr int NSTG   = (NW >= 256) ? 2 : 3;
    constexpr int FS     = NW + NW / 32;      // fbuf row stride
    constexpr int NC     = KDIM / 64;
    constexpr int KOFF   = TABLE ? 0 : EE;

    extern __shared__ char smem[];
    const uint32_t sbase = smem_u32(smem);
    const int tid = threadIdx.x;
    const int lane = tid & 31, wid = tid >> 5;
    const int wm = wid >> 2, wn = wid & 3;    // warp grid 4(m) x 4(n)
    const int mtile = blockIdx.y;
    const int n0    = blockIdx.x * NW;        // TABLE: col base
    const int kbase = blockIdx.x * WN;        // FUSED: k base within H

    const __nv_bfloat16* gAh = (TABLE ? g_Eh : &g_Ah[rp][0]) + (size_t)(mtile * 128) * KDIM;
    const __nv_bfloat16* gAl = (TABLE ? g_El : &g_Al[rp][0]) + (size_t)(mtile * 128) * KDIM;

    // ---- stage loader: A(hi/lo) 128x64, B(hi/lo) NWx64 ----
    auto load_stage = [&](int kc, int s) {
        const uint32_t sb = sbase + s * STAGE;
        #pragma unroll
        for (int i = 0; i < 2; i++) {
            int cid = tid + i * 512;                 // 0..1023 = 128 rows x 8 chunks
            int row = cid >> 3, ch = cid & 7;
            uint32_t so = row * 144 + ch * 16;
            const size_t ga = (size_t)row * KDIM + kc * 64 + ch * 8;
            cp_async16(sb + so,          gAh + ga);
            cp_async16(sb + ASPLIT + so, gAl + ga);
        }
        #pragma unroll
        for (int i = 0; i < NW / 64; i++) {
            int cid = tid + i * 512;                 // NW rows x 8 chunks
            int j = cid >> 3, ch = cid & 7;
            int gn = TABLE ? (n0 + j) : (((j / WN) << 9) + kbase + (j % WN));
            const size_t gb = (size_t)gn * KTOT + KOFF + kc * 64 + ch * 8;
            cp_async16(sb + BOFF + j * 144 + ch * 16,          g_WTh + gb);
            cp_async16(sb + BOFF + BSPLIT + j * 144 + ch * 16, g_WTl + gb);
        }
    };

    float acc[2][NT][4] = {};

    #pragma unroll
    for (int s = 0; s < NSTG - 1; s++) { load_stage(s, s); CP_COMMIT(); }

    for (int c = 0; c < NC; c++) {
        if constexpr (NSTG == 3) CP_WAIT(1); else CP_WAIT(0);
        __syncthreads();
        if (c + NSTG - 1 < NC) load_stage(c + NSTG - 1, (c + NSTG - 1) % NSTG);
        CP_COMMIT();

        const uint32_t sb = sbase + (c % NSTG) * STAGE;
        #pragma unroll
        for (int k16 = 0; k16 < 4; k16++) {
            uint32_t ah[2][4], al[2][4], bfr[NT][2];
            #pragma unroll
            for (int mt = 0; mt < 2; mt++) {
                uint32_t addr = sb + (wm * 32 + mt * 16 + (lane & 15)) * 144
                              + k16 * 32 + ((lane >> 4) & 1) * 16;
                LDSM4(ah[mt], addr);
                LDSM4(al[mt], addr + ASPLIT);
            }
            // B hi
            #pragma unroll
            for (int bt = 0; bt < NT / 2; bt++) {
                int nrow = wn * WN + bt * 16 + ((lane >> 4) & 1) * 8 + (lane & 7);
                uint32_t addr = sb + BOFF + nrow * 144 + k16 * 32 + ((lane >> 3) & 1) * 16;
                uint32_t t4[4];
                LDSM4(t4, addr);
                bfr[2 * bt][0] = t4[0]; bfr[2 * bt][1] = t4[1];
                bfr[2 * bt + 1][0] = t4[2]; bfr[2 * bt + 1][1] = t4[3];
            }
            #pragma unroll
            for (int mt = 0; mt < 2; mt++)
                #pragma unroll
                for (int nt = 0; nt < NT; nt++)
                    MMA16816(acc[mt][nt], ah[mt], bfr[nt]);
            #pragma unroll
            for (int mt = 0; mt < 2; mt++)
                #pragma unroll
                for (int nt = 0; nt < NT; nt++)
                    MMA16816(acc[mt][nt], al[mt], bfr[nt]);
            // B lo (reuse regs)
            #pragma unroll
            for (int bt = 0; bt < NT / 2; bt++) {
                int nrow = wn * WN + bt * 16 + ((lane >> 4) & 1) * 8 + (lane & 7);
                uint32_t addr = sb + BOFF + BSPLIT + nrow * 144 + k16 * 32 + ((lane >> 3) & 1) * 16;
                uint32_t t4[4];
                LDSM4(t4, addr);
                bfr[2 * bt][0] = t4[0]; bfr[2 * bt][1] = t4[1];
                bfr[2 * bt + 1][0] = t4[2]; bfr[2 * bt + 1][1] = t4[3];
            }
            #pragma unroll
            for (int mt = 0; mt < 2; mt++)
                #pragma unroll
                for (int nt = 0; nt < NT; nt++)
                    MMA16816(acc[mt][nt], ah[mt], bfr[nt]);
        }
    }

    if constexpr (TABLE) {
        // direct frag store: ptab = acc + bias
        #pragma unroll
        for (int mt = 0; mt < 2; mt++) {
            #pragma unroll
            for (int nt = 0; nt < NT; nt++) {
                int col = n0 + wn * WN + nt * 8 + (lane & 3) * 2;
                int r0 = mtile * 128 + wm * 32 + mt * 16 + (lane >> 2);
                float b0 = g_bc[col], b1 = g_bc[col + 1];
                if (r0 < mrows) {
                    float2 v = make_float2(acc[mt][nt][0] + b0, acc[mt][nt][1] + b1);
                    *(float2*)&g_ptab[(size_t)r0 * COLS + col] = v;
                }
                if (r0 + 8 < mrows) {
                    float2 v = make_float2(acc[mt][nt][2] + b0, acc[mt][nt][3] + b1);
                    *(float2*)&g_ptab[(size_t)(r0 + 8) * COLS + col] = v;
                }
            }
        }
    } else {
        // stage acc -> smem, then fused gate + hsum-split epilogue
        __syncthreads();
        float* fbuf = (float*)smem;                  // [128][FS]
        #pragma unroll
        for (int mt = 0; mt < 2; mt++) {
            #pragma unroll
            for (int nt = 0; nt < NT; nt++) {
                int col = wn * WN + nt * 8 + (lane & 3) * 2;
                int r0 = wm * 32 + mt * 16 + (lane >> 2);
                fbuf[r0 * FS + col]           = acc[mt][nt][0];
                fbuf[r0 * FS + col + 1]       = acc[mt][nt][1];
                fbuf[(r0 + 8) * FS + col]     = acc[mt][nt][2];
                fbuf[(r0 + 8) * FS + col + 1] = acc[mt][nt][3];
            }
        }
        __syncthreads();
        if (base == 0) {
            // root: rows 0..63 valid, write out only. 64*WN elements / 512 threads.
            #pragma unroll
            for (int i = 0; i < WN / 8; i++) {
                int e = tid + i * 512;               // 0..64*WN-1
                int b = e / WN, q = e % WN;
                if (b >= 64) continue;
                int k = kbase + q;
                int tok = ast[b * NNODE];            // node 0
                const float* p = g_ptab + (size_t)tok * COLS + k;
                const float* fr = fbuf + b * FS + q;
                float xi = fr[0]      + p[0];
                float xo = fr[WN]     + p[HH];
                float xu = fr[2 * WN] + p[2 * HH];
                float xf = fr[3 * WN] + p[3 * HH];
                size_t ca = ((size_t)1 * 64 + b) * HH + k;     // children 1, 2
                float cs = g_c[ca] + g_c[ca + 64 * HH];
                float cc = fmaf(sigf(xf), cs, sigf(xi) * tanhff(xu));
                out[(size_t)b * HH + k] = sigf(xo) * tanhff(cc);
            }
        } else {
            const int node1 = base + mtile * 2;      // odd = 2p+1; sibling node1+1
            __nv_bfloat16* wAh = &g_Ah[rp ^ 1][0];
            __nv_bfloat16* wAl = &g_Al[rp ^ 1][0];
            #pragma unroll
            for (int i = 0; i < WN / 8; i++) {
                int e = tid + i * 512;               // 0..64*WN-1
                int b = e / WN, q = e % WN;
                int k = kbase + q;
                int tok1 = ast[b * NNODE + node1];
                int tok2 = ast[b * NNODE + node1 + 1];
                const float* p1 = g_ptab + (size_t)tok1 * COLS + k;
                const float* p2 = g_ptab + (size_t)tok2 * COLS + k;
                const float* f1 = fbuf + b * FS + q;
                const float* f2 = fbuf + (b + 64) * FS + q;
                size_t ca = ((size_t)(2 * node1 + 1) * 64 + b) * HH + k;
                float cs1 = g_c[ca] + g_c[ca + 64 * HH];
                size_t cb = ((size_t)(2 * node1 + 3) * 64 + b) * HH + k;
                float cs2 = g_c[cb] + g_c[cb + 64 * HH];
                float cc1 = fmaf(sigf(f1[3 * WN] + p1[3 * HH]), cs1,
                                 sigf(f1[0] + p1[0]) * tanhff(f1[2 * WN] + p1[2 * HH]));
                float hh1 = sigf(f1[WN] + p1[HH]) * tanhff(cc1);
                float cc2 = fmaf(sigf(f2[3 * WN] + p2[3 * HH]), cs2,
                                 sigf(f2[0] + p2[0]) * tanhff(f2[2 * WN] + p2[2 * HH]));
                float hh2 = sigf(f2[WN] + p2[HH]) * tanhff(cc2);
                size_t gi1 = ((size_t)node1 * 64 + b) * HH + k;
                g_c[gi1] = cc1;
                g_c[gi1 + 64 * HH] = cc2;
                __nv_bfloat16 hi, lo; split2(hh1 + hh2, hi, lo);
                size_t po = (size_t)(mtile * 64 + b) * HH + k;   // parent local row
                wAh[po] = hi;
                wAl[po] = lo;
            }
        }
    }
}

// ---------------- launch ----------------
extern "C" void kernel_launch(void* const* d_in, const int* in_sizes, int n_in,
                              void* d_out, int out_size) {
    const int*   ast   = (const int*)d_in[0];
    // d_in[1] = parent (structurally (i-1)/2, unused)
    const float* emb   = (const float*)d_in[2];
    const float* W_iou = (const float*)d_in[3];
    const float* b_iou = (const float*)d_in[4];
    const float* W_f   = (const float*)d_in[5];
    const float* b_f   = (const float*)d_in[6];
    float* out = (float*)d_out;
    (void)in_sizes; (void)n_in; (void)out_size;

    constexpr int SMEM64  = (36864 + 2 * 64 * 144) * 3;    // 165888
    constexpr int SMEM128 = (36864 + 2 * 128 * 144) * 3;   // 221184
    constexpr int SMEM256 = (36864 + 2 * 256 * 144) * 2;   // 221184
    cudaFuncSetAttribute(mma_gemm<EE, true, 256>,  cudaFuncAttributeMaxDynamicSharedMemorySize, SMEM256);
    cudaFuncSetAttribute(mma_gemm<HH, false, 64>,  cudaFuncAttributeMaxDynamicSharedMemorySize, SMEM64);
    cudaFuncSetAttribute(mma_gemm<HH, false, 128>, cudaFuncAttributeMaxDynamicSharedMemorySize, SMEM128);
    cudaFuncSetAttribute(mma_gemm<HH, false, 256>, cudaFuncAttributeMaxDynamicSharedMemorySize, SMEM256);

    packT_kernel<<<dim3(COLS / 32, KTOT / 32), dim3(32, 8)>>>(W_iou, W_f);
    esplit_kernel<<<(2048 * EE + 255) / 256, 256>>>(emb, b_iou, b_f);

    // ptab = emb_table @ Wx + bias : M=2000 (pad 2048), K=256, N=2048
    {
        dim3 grid(COLS / 256, 16);
        mma_gemm<EE, true, 256><<<grid, 512, SMEM256>>>(nullptr, 0, VOCAB, nullptr, 0);
    }

    // leaves: gates + parent hsum-split into buf 0
    leaf_gate<<<(256 * 64 * (HH / 4) + 255) / 256, 256>>>(ast);

    // levels 8..0: fused GEMM + gates + next-level hsum-split
    for (int d = 8; d >= 0; d--) {
        int L = 1 << d;
        int base = L - 1;
        int M = 64 * L;
        int mtiles = (M + 127) / 128;
        if (d >= 5) {
            dim3 grid(HH / 64, mtiles);
            mma_gemm<HH, false, 256><<<grid, 512, SMEM256>>>(ast, base, M, nullptr, d & 1);
        } else if (d == 4) {
            dim3 grid(HH / 32, mtiles);
            mma_gemm<HH, false, 128><<<grid, 512, SMEM128>>>(ast, base, M, nullptr, d & 1);
        } else {
            dim3 grid(HH / 16, mtiles);
            mma_gemm<HH, false, 64><<<grid, 512, SMEM64>>>(ast, base, M, (d == 0) ? out : nullptr, d & 1);
        }
    }
}